// round 5
// baseline (speedup 1.0000x reference)
#include <cuda_runtime.h>
#include <cuda_bf16.h>

#define B_ 512
#define T_ 512
#define N_ 64

#define L2E 1.4426950408889634f   // log2(e)
#define LN2 0.6931471805599453f   // ln(2)

// ---- packed f32x2 + MUFU helpers (sm_103a) ----
__device__ __forceinline__ void ffma2(unsigned long long &d,
                                      unsigned long long a,
                                      unsigned long long b) {
    asm("fma.rn.f32x2 %0, %1, %2, %0;" : "+l"(d) : "l"(a), "l"(b));
}
__device__ __forceinline__ unsigned long long fadd2(unsigned long long a,
                                                    unsigned long long b) {
    unsigned long long d;
    asm("add.rn.f32x2 %0, %1, %2;" : "=l"(d) : "l"(a), "l"(b));
    return d;
}
__device__ __forceinline__ unsigned long long pack2(float lo, float hi) {
    unsigned long long d;
    asm("mov.b64 %0, {%1, %2};" : "=l"(d) : "f"(lo), "f"(hi));
    return d;
}
__device__ __forceinline__ void unpack2(unsigned long long v, float &lo, float &hi) {
    asm("mov.b64 {%0, %1}, %2;" : "=f"(lo), "=f"(hi) : "l"(v));
}
__device__ __forceinline__ float ex2(float x) {
    float r; asm("ex2.approx.f32 %0, %1;" : "=f"(r) : "f"(x)); return r;
}
__device__ __forceinline__ float lg2(float x) {
    float r; asm("lg2.approx.f32 %0, %1;" : "=f"(r) : "f"(x)); return r;
}
// Pair-local barrier: named barrier over 64 threads (one batch's two warps).
__device__ __forceinline__ void pair_bar(int id) {
    asm volatile("bar.sync %0, 64;" :: "r"(id) : "memory");
}

__device__ int d_order[B_];

// Rank batches by length descending (ties by index) -> deterministic permutation.
// grid = 512 blocks x 32 threads; block b computes rank of batch b.
__global__ void rank_kernel(const int* __restrict__ lens) {
    const int b = blockIdx.x;
    const int lane = threadIdx.x;
    const int lb = __ldg(&lens[b]);
    int r = 0;
#pragma unroll 4
    for (int k = lane * 16; k < lane * 16 + 16; k++) {
        const int lk = __ldg(&lens[k]);
        r += (lk > lb) || (lk == lb && k < b);
    }
#pragma unroll
    for (int off = 16; off; off >>= 1)
        r += __shfl_xor_sync(0xffffffffu, r, off);
    if (lane == 0) d_order[r] = b;
}

// 128-thread blocks, TWO independent batches per block:
//   warps 0,1 (SMSP 0,1) -> batch order[bid]       (pair 0)
//   warps 2,3 (SMSP 2,3) -> batch order[511-bid]   (pair 1)
// Pairing rank r with rank 511-r balances per-block work; pair-local named
// barriers keep the two recursions fully decoupled. All 4 SMSPs are used
// (64-thread blocks only ever touched SMSP 0/1 — warp_id % 4).
//
// Linear-domain recursion per pair (thread j of the pair owns tag-column j,
// A[i][j] = exp2(trans[i][j]*L2E) register-resident, packed over i):
//   v_t[j] = ex2(emit2[t][j] - q_t) * sum_i v_{t-1}[i] * A[i][j]
//   q_t    = floor-log2 of v_{t-1}[0] (exponent bit-extract, 3 ALU ops) + 6
// One STS + one pair-barrier + 16 broadcast LDS.128 + 32 FFMA2 per step.
__global__ __launch_bounds__(128) void crf_fwd(
    const float* __restrict__ inputs,   // [B, T, N]
    const float* __restrict__ trans,    // [N, N]
    const int*   __restrict__ tags,     // [B, T]
    const int*   __restrict__ lens,     // [B]
    float*       __restrict__ out)      // [B + N*N]
{
    const int pair = threadIdx.x >> 6;        // 0 or 1
    const int j    = threadIdx.x & 63;        // tag column within the pair
    const int lane = threadIdx.x & 31;
    const int wpin = j >> 5;                  // warp within pair (0/1)
    const int barid = pair + 1;

    const int b = d_order[pair ? (B_ - 1 - blockIdx.x) : blockIdx.x];

    __shared__ __align__(16) float Esh[2][2][68];   // [pair][buf][vec]
    __shared__ float red[2][2];

    // Passthrough copy of transition_params: 256 blocks x 4 float4 = 4096 floats.
    if (threadIdx.x < 4) {
        const int idx = blockIdx.x * 4 + threadIdx.x;
        reinterpret_cast<float4*>(out + B_)[idx] =
            reinterpret_cast<const float4*>(trans)[idx];
    }

    // Register-resident A[i][j] = exp2(trans[i][j] * L2E), packed over i.
    unsigned long long ETp[N_ / 2];
#pragma unroll
    for (int m = 0; m < N_ / 2; m++) {
        const float lo = ex2(trans[(2 * m) * N_ + j] * L2E);
        const float hi = ex2(trans[(2 * m + 1) * N_ + j] * L2E);
        ETp[m] = pack2(lo, hi);
    }

    const float* emit = inputs + (size_t)b * T_ * N_;
    const int len = lens[b];
    const int steps = (len > 1) ? (len - 1) : 0;

    // t = 0: v0[j] = exp2(emit2[0][j] - r0), r0 = emit2[0][0].
    const float r0 = __ldg(&emit[0]) * L2E;
    float R = r0;                                   // accumulated log2 shift
    float v = ex2(fmaf(emit[j], L2E, -r0));
    Esh[pair][0][j] = v;

    // Raw emission prefetch (distance 2); L2E scale folded into the ex2 arg.
    float ec = (steps >= 1) ? emit[N_ + j] : 0.0f;
    float en = (steps >= 2) ? emit[2 * N_ + j] : 0.0f;

    pair_bar(barid);

    for (int t = 1; t <= steps; t++) {
        const float e_nn = (t + 2 <= steps) ? emit[(t + 2) * N_ + j] : 0.0f;
        const int buf = (t - 1) & 1;

        // Off-chain rescale: q = floor(log2(E0)) + 6 via exponent bits (exact
        // common shift; E0 is in exp2(+-45) so exponent is always in range).
        const float E0 = Esh[pair][buf][0];
        const float q = (float)((int)((__float_as_uint(E0) >> 23) & 0xFF) - 121);
        const float ms = ex2(fmaf(ec, L2E, -q));
        R += q;

        // GEMV: s_j = sum_i v[i] * A[i][j]; 16 broadcast LDS.128, 32 FFMA2.
        const ulonglong2* ev = reinterpret_cast<const ulonglong2*>(&Esh[pair][buf][0]);
        unsigned long long a0 = 0ull, a1 = 0ull, a2 = 0ull, a3 = 0ull;
        unsigned long long a4 = 0ull, a5 = 0ull, a6 = 0ull, a7 = 0ull;
#pragma unroll
        for (int m = 0; m < 4; m++) {
            const ulonglong2 p0 = ev[4 * m + 0];
            const ulonglong2 p1 = ev[4 * m + 1];
            const ulonglong2 p2 = ev[4 * m + 2];
            const ulonglong2 p3 = ev[4 * m + 3];
            ffma2(a0, p0.x, ETp[8 * m + 0]);
            ffma2(a1, p0.y, ETp[8 * m + 1]);
            ffma2(a2, p1.x, ETp[8 * m + 2]);
            ffma2(a3, p1.y, ETp[8 * m + 3]);
            ffma2(a4, p2.x, ETp[8 * m + 4]);
            ffma2(a5, p2.y, ETp[8 * m + 5]);
            ffma2(a6, p3.x, ETp[8 * m + 6]);
            ffma2(a7, p3.y, ETp[8 * m + 7]);
        }
        const unsigned long long sA =
            fadd2(fadd2(fadd2(a0, a1), fadd2(a2, a3)),
                  fadd2(fadd2(a4, a5), fadd2(a6, a7)));
        float slo, shi;
        unpack2(sA, slo, shi);

        v = ms * (slo + shi);
        Esh[pair][buf ^ 1][j] = v;

        ec = en;
        en = e_nn;
        pair_bar(barid);                     // single pair-local barrier per step
    }

    // logZ = (R + lg2(sum_j v[j])) * ln2.
    float s = v;
#pragma unroll
    for (int off = 16; off; off >>= 1)
        s += __shfl_xor_sync(0xffffffffu, s, off);
    if (lane == 0) red[pair][wpin] = s;
    pair_bar(barid);
    const float logZ = (R + lg2(red[pair][0] + red[pair][1])) * LN2;

    // Sequence score: unary (t in [0,len)) + binary (t in [1,len)).
    const int* btags = tags + b * T_;
    float sc = 0.0f;
    for (int t = j; t < len; t += N_)
        sc += emit[t * N_ + btags[t]];
    for (int t = j + 1; t < len; t += N_)
        sc += trans[btags[t - 1] * N_ + btags[t]];

#pragma unroll
    for (int off = 16; off; off >>= 1)
        sc += __shfl_xor_sync(0xffffffffu, sc, off);
    pair_bar(barid);                 // all logZ reads of red must complete first
    if (lane == 0) red[pair][wpin] = sc;
    pair_bar(barid);
    if (j == 0) out[b] = (red[pair][0] + red[pair][1]) - logZ;
}

extern "C" void kernel_launch(void* const* d_in, const int* in_sizes, int n_in,
                              void* d_out, int out_size) {
    const float* inputs = (const float*)d_in[0];   // [512, 512, 64] f32
    const float* trans  = (const float*)d_in[1];   // [64, 64] f32
    const int*   tags   = (const int*)d_in[2];     // [512, 512] i32
    const int*   lens   = (const int*)d_in[3];     // [512] i32
    float*       out    = (float*)d_out;           // [512 + 4096] f32

    rank_kernel<<<B_, 32>>>(lens);
    crf_fwd<<<B_ / 2, 128>>>(inputs, trans, tags, lens, out);
}

// round 6
// speedup vs baseline: 1.0524x; 1.0524x over previous
#include <cuda_runtime.h>
#include <cuda_bf16.h>

#define B_ 512
#define T_ 512
#define N_ 64

#define L2E 1.4426950408889634f   // log2(e)
#define LN2 0.6931471805599453f   // ln(2)

// ---- packed f32x2 + MUFU helpers (sm_103a) ----
__device__ __forceinline__ void ffma2(unsigned long long &d,
                                      unsigned long long a,
                                      unsigned long long b) {
    asm("fma.rn.f32x2 %0, %1, %2, %0;" : "+l"(d) : "l"(a), "l"(b));
}
__device__ __forceinline__ unsigned long long fadd2(unsigned long long a,
                                                    unsigned long long b) {
    unsigned long long d;
    asm("add.rn.f32x2 %0, %1, %2;" : "=l"(d) : "l"(a), "l"(b));
    return d;
}
__device__ __forceinline__ unsigned long long pack2(float lo, float hi) {
    unsigned long long d;
    asm("mov.b64 %0, {%1, %2};" : "=l"(d) : "f"(lo), "f"(hi));
    return d;
}
__device__ __forceinline__ void unpack2(unsigned long long v, float &lo, float &hi) {
    asm("mov.b64 {%0, %1}, %2;" : "=f"(lo), "=f"(hi) : "l"(v));
}
__device__ __forceinline__ float ex2(float x) {
    float r; asm("ex2.approx.f32 %0, %1;" : "=f"(r) : "f"(x)); return r;
}
__device__ __forceinline__ float lg2(float x) {
    float r; asm("lg2.approx.f32 %0, %1;" : "=f"(r) : "f"(x)); return r;
}

// ONE batch per 128-thread block (4 warps on 4 SMSPs).
// Warp w owns tag-columns [16w, 16w+16). Lane k computes the i-half
// [32*(k>=16), +32) of column 16w + (k&15): 8 broadcast LDS.128 + 16 FFMA2,
// then one shfl_xor(16) combines the halves; lanes 0-15 scale + STS.
//
// Linear-domain recursion (no exp/log on the serial chain):
//   v_t[c] = ex2(emit2[t][c] - q_t) * sum_i v_{t-1}[i] * A[i][c]
//   A[i][c] = exp2(trans[i][c]*L2E) register-resident (16 packed f32x2/thread)
//   q_t = floor-log2(v_{t-1}[0]) + 7 via exponent bit-extract (off-chain).
// One __syncthreads per step; per-thread GEMV issue is 24 instrs (half of the
// 2-warp layout), executed in parallel on all 4 SMSPs.
__global__ __launch_bounds__(128) void crf_fwd(
    const float* __restrict__ inputs,   // [B, T, N]
    const float* __restrict__ trans,    // [N, N]
    const int*   __restrict__ tags,     // [B, T]
    const int*   __restrict__ lens,     // [B]
    float*       __restrict__ out)      // [B + N*N]
{
    const int b    = blockIdx.x;
    const int tid  = threadIdx.x;
    const int wid  = tid >> 5;
    const int lane = tid & 31;
    const int col  = 16 * wid + (lane & 15);   // owned tag-column
    const int half = lane >> 4;                // i-half: 0 -> [0,32), 1 -> [32,64)
    const int i0   = 32 * half;

    __shared__ __align__(16) float Esh[2][68];  // double-buffered v vector
    __shared__ float red[4];

    // Passthrough copy of transition_params (512 blocks x 8 elems = 4096).
    if (tid < 8) {
        const int idx = b * 8 + tid;
        out[B_ + idx] = trans[idx];
    }

    // Register-resident A[i][col] = exp2(trans[i][col]*L2E) for i in [i0, i0+32),
    // packed over i: 16 f32x2 registers.
    unsigned long long ETp[16];
#pragma unroll
    for (int m = 0; m < 16; m++) {
        const int i = i0 + 2 * m;
        const float lo = ex2(trans[i * N_ + col] * L2E);
        const float hi = ex2(trans[(i + 1) * N_ + col] * L2E);
        ETp[m] = pack2(lo, hi);
    }

    const float* emit = inputs + (size_t)b * T_ * N_;
    const int len = lens[b];
    const int steps = (len > 1) ? (len - 1) : 0;   // last_index = max(0, len-1)

    // t = 0: v0[j] = exp2(emit2[0][j] - r0), r0 = emit2[0][0].
    const float r0 = __ldg(&emit[0]) * L2E;
    float R = r0;                                   // accumulated log2 shift
    if (tid < N_)
        Esh[0][tid] = ex2(fmaf(emit[tid], L2E, -r0));

    // Raw emission prefetch for the owned column (distance 2).
    float ec = (steps >= 1) ? emit[N_ + col] : 0.0f;
    float en = (steps >= 2) ? emit[2 * N_ + col] : 0.0f;

    __syncthreads();

    for (int t = 1; t <= steps; t++) {
        const float e_nn = (t + 2 <= steps) ? emit[(t + 2) * N_ + col] : 0.0f;
        const int buf = (t - 1) & 1;

        // Off-chain rescale from v_{t-1}[0]'s exponent bits (exact common shift).
        const float E0 = Esh[buf][0];
        const float q = (float)((int)((__float_as_uint(E0) >> 23) & 0xFF) - 121);
        const float ms = ex2(fmaf(ec, L2E, -q));
        R += q;

        // Half-GEMV: partial_c = sum_{i in half} v[i] * A[i][c].
        // 8 broadcast LDS.128, 16 FFMA2, 4 accumulators (depth 4).
        const ulonglong2* ev =
            reinterpret_cast<const ulonglong2*>(&Esh[buf][i0]);
        unsigned long long a0 = 0ull, a1 = 0ull, a2 = 0ull, a3 = 0ull;
#pragma unroll
        for (int m = 0; m < 4; m++) {
            const ulonglong2 p0 = ev[2 * m + 0];   // v[i0+8m   .. +3]
            const ulonglong2 p1 = ev[2 * m + 1];   // v[i0+8m+4 .. +7]
            ffma2(a0, p0.x, ETp[4 * m + 0]);
            ffma2(a1, p0.y, ETp[4 * m + 1]);
            ffma2(a2, p1.x, ETp[4 * m + 2]);
            ffma2(a3, p1.y, ETp[4 * m + 3]);
        }
        const unsigned long long sA = fadd2(fadd2(a0, a1), fadd2(a2, a3));
        float slo, shi;
        unpack2(sA, slo, shi);
        float s = slo + shi;

        // Combine the two i-halves of this column (lanes k <-> k+16).
        s += __shfl_xor_sync(0xffffffffu, s, 16);

        if (lane < 16)
            Esh[buf ^ 1][col] = ms * s;

        ec = en;
        en = e_nn;
        __syncthreads();                     // single barrier per step
    }

    // logZ = (R + lg2(sum_j v_last[j])) * ln2. Final vector sits in Esh[steps&1].
    float fs = (tid < N_) ? Esh[steps & 1][tid] : 0.0f;
#pragma unroll
    for (int off = 16; off; off >>= 1)
        fs += __shfl_xor_sync(0xffffffffu, fs, off);
    if (lane == 0) red[wid] = fs;
    __syncthreads();
    const float logZ =
        (R + lg2(red[0] + red[1] + red[2] + red[3])) * LN2;

    // Sequence score: unary (t in [0,len)) + binary (t in [1,len)),
    // strided over all 128 threads.
    const int* btags = tags + b * T_;
    float sc = 0.0f;
    for (int t = tid; t < len; t += 128)
        sc += emit[t * N_ + btags[t]];
    for (int t = tid + 1; t < len; t += 128)
        sc += trans[btags[t - 1] * N_ + btags[t]];

#pragma unroll
    for (int off = 16; off; off >>= 1)
        sc += __shfl_xor_sync(0xffffffffu, sc, off);
    __syncthreads();               // all logZ reads of red must complete first
    if (lane == 0) red[wid] = sc;
    __syncthreads();
    if (tid == 0)
        out[b] = (red[0] + red[1] + red[2] + red[3]) - logZ;
}

extern "C" void kernel_launch(void* const* d_in, const int* in_sizes, int n_in,
                              void* d_out, int out_size) {
    const float* inputs = (const float*)d_in[0];   // [512, 512, 64] f32
    const float* trans  = (const float*)d_in[1];   // [64, 64] f32
    const int*   tags   = (const int*)d_in[2];     // [512, 512] i32
    const int*   lens   = (const int*)d_in[3];     // [512] i32
    float*       out    = (float*)d_out;           // [512 + 4096] f32

    crf_fwd<<<B_, 128>>>(inputs, trans, tags, lens, out);
}

// round 7
// speedup vs baseline: 1.1048x; 1.0498x over previous
#include <cuda_runtime.h>
#include <cuda_bf16.h>

#define B_ 512
#define T_ 512
#define N_ 64

#define L2E 1.4426950408889634f   // log2(e)
#define LN2 0.6931471805599453f   // ln(2)

// ---- packed f32x2 + MUFU helpers (sm_103a) ----
__device__ __forceinline__ void ffma2(unsigned long long &d,
                                      unsigned long long a,
                                      unsigned long long b) {
    asm("fma.rn.f32x2 %0, %1, %2, %0;" : "+l"(d) : "l"(a), "l"(b));
}
__device__ __forceinline__ unsigned long long fadd2(unsigned long long a,
                                                    unsigned long long b) {
    unsigned long long d;
    asm("add.rn.f32x2 %0, %1, %2;" : "=l"(d) : "l"(a), "l"(b));
    return d;
}
__device__ __forceinline__ unsigned long long pack2(float lo, float hi) {
    unsigned long long d;
    asm("mov.b64 %0, {%1, %2};" : "=l"(d) : "f"(lo), "f"(hi));
    return d;
}
__device__ __forceinline__ void unpack2(unsigned long long v, float &lo, float &hi) {
    asm("mov.b64 {%0, %1}, %2;" : "=f"(lo), "=f"(hi) : "l"(v));
}
__device__ __forceinline__ float ex2(float x) {
    float r; asm("ex2.approx.f32 %0, %1;" : "=f"(r) : "f"(x)); return r;
}
__device__ __forceinline__ float lg2(float x) {
    float r; asm("lg2.approx.f32 %0, %1;" : "=f"(r) : "f"(x)); return r;
}

// ONE batch per 128-thread block (4 warps / 4 SMSPs).
// Warp w owns tag-columns [16w, 16w+16); lane k handles i-half [32*(k>=16), +32)
// of column 16w + (k&15): 8 broadcast LDS.128 + 16 FFMA2, shfl_xor(16) combine.
//
// Linear-domain recursion, UNROLLED BY 2 with rescale amortized to every other
// step (exact power-of-2 shift; v stays within 2^+-45, intermediates 2^+-52):
//   step A (t odd):  v1[c] = ex2(emit2[t][c]   - q) * sum_i v0[i] A[i][c]
//                    q = floor(log2(v0[0])) + 6 (exponent bit-extract), R += q
//   step B (t even): v0[c] = ex2(emit2[t+1][c])    * sum_i v1[i] A[i][c]
// Static double-buffer (A: Esh[0]->Esh[1], B: Esh[1]->Esh[0]); one
// __syncthreads per step; overhead instructions cut ~25% vs per-step rescale.
__global__ __launch_bounds__(128) void crf_fwd(
    const float* __restrict__ inputs,   // [B, T, N]
    const float* __restrict__ trans,    // [N, N]
    const int*   __restrict__ tags,     // [B, T]
    const int*   __restrict__ lens,     // [B]
    float*       __restrict__ out)      // [B + N*N]
{
    const int b    = blockIdx.x;
    const int tid  = threadIdx.x;
    const int wid  = tid >> 5;
    const int lane = tid & 31;
    const int col  = 16 * wid + (lane & 15);   // owned tag-column
    const int i0   = (lane >> 4) << 5;         // i-half base: 0 or 32

    __shared__ __align__(16) float Esh[2][68];  // double-buffered v vector
    __shared__ float red[4];

    // Passthrough copy of transition_params (512 blocks x 8 elems = 4096).
    if (tid < 8) {
        const int idx = b * 8 + tid;
        out[B_ + idx] = trans[idx];
    }

    // Register-resident A[i][col] = exp2(trans[i][col]*L2E), i in [i0, i0+32).
    unsigned long long ETp[16];
#pragma unroll
    for (int m = 0; m < 16; m++) {
        const int i = i0 + 2 * m;
        const float lo = ex2(trans[i * N_ + col] * L2E);
        const float hi = ex2(trans[(i + 1) * N_ + col] * L2E);
        ETp[m] = pack2(lo, hi);
    }

    const float* emit = inputs + (size_t)b * T_ * N_;
    const int len = lens[b];
    const int steps = (len > 1) ? (len - 1) : 0;   // last_index = max(0, len-1)

    // t = 0: v0[j] = exp2(emit2[0][j] - r0), r0 = emit2[0][0].
    const float r0 = __ldg(&emit[0]) * L2E;
    float R = r0;                                   // accumulated log2 shift
    if (tid < N_)
        Esh[0][tid] = ex2(fmaf(emit[tid], L2E, -r0));

    // Emission prefetch for the owned column (distance: one pair ahead).
    float ecA = (steps >= 1) ? emit[N_ + col] : 0.0f;
    float ecB = (steps >= 2) ? emit[2 * N_ + col] : 0.0f;

    __syncthreads();

    int t = 1;
    for (; t + 1 <= steps; t += 2) {
        // Prefetch the next pair's emissions.
        const float eA = (t + 2 <= steps) ? emit[(t + 2) * N_ + col] : 0.0f;
        const float eB = (t + 3 <= steps) ? emit[(t + 3) * N_ + col] : 0.0f;

        // ---- step A (rescaled): Esh[0] -> Esh[1] ----
        {
            const float E0 = Esh[0][0];
            const float q = (float)((int)((__float_as_uint(E0) >> 23) & 0xFF) - 121);
            const float ms = ex2(fmaf(ecA, L2E, -q));
            R += q;

            const ulonglong2* ev = reinterpret_cast<const ulonglong2*>(&Esh[0][i0]);
            unsigned long long a0 = 0ull, a1 = 0ull, a2 = 0ull, a3 = 0ull;
#pragma unroll
            for (int m = 0; m < 4; m++) {
                const ulonglong2 p0 = ev[2 * m + 0];
                const ulonglong2 p1 = ev[2 * m + 1];
                ffma2(a0, p0.x, ETp[4 * m + 0]);
                ffma2(a1, p0.y, ETp[4 * m + 1]);
                ffma2(a2, p1.x, ETp[4 * m + 2]);
                ffma2(a3, p1.y, ETp[4 * m + 3]);
            }
            float slo, shi;
            unpack2(fadd2(fadd2(a0, a1), fadd2(a2, a3)), slo, shi);
            float s = slo + shi;
            s += __shfl_xor_sync(0xffffffffu, s, 16);
            if (lane < 16) Esh[1][col] = ms * s;
            __syncthreads();
        }

        // ---- step B (no rescale): Esh[1] -> Esh[0] ----
        {
            const float ms = ex2(ecB * L2E);

            const ulonglong2* ev = reinterpret_cast<const ulonglong2*>(&Esh[1][i0]);
            unsigned long long a0 = 0ull, a1 = 0ull, a2 = 0ull, a3 = 0ull;
#pragma unroll
            for (int m = 0; m < 4; m++) {
                const ulonglong2 p0 = ev[2 * m + 0];
                const ulonglong2 p1 = ev[2 * m + 1];
                ffma2(a0, p0.x, ETp[4 * m + 0]);
                ffma2(a1, p0.y, ETp[4 * m + 1]);
                ffma2(a2, p1.x, ETp[4 * m + 2]);
                ffma2(a3, p1.y, ETp[4 * m + 3]);
            }
            float slo, shi;
            unpack2(fadd2(fadd2(a0, a1), fadd2(a2, a3)), slo, shi);
            float s = slo + shi;
            s += __shfl_xor_sync(0xffffffffu, s, 16);
            if (lane < 16) Esh[0][col] = ms * s;
            __syncthreads();
        }

        ecA = eA;
        ecB = eB;
    }

    // Odd leftover step (t == steps): rescaled, Esh[0] -> Esh[1].
    if (t <= steps) {
        const float E0 = Esh[0][0];
        const float q = (float)((int)((__float_as_uint(E0) >> 23) & 0xFF) - 121);
        const float ms = ex2(fmaf(ecA, L2E, -q));
        R += q;

        const ulonglong2* ev = reinterpret_cast<const ulonglong2*>(&Esh[0][i0]);
        unsigned long long a0 = 0ull, a1 = 0ull, a2 = 0ull, a3 = 0ull;
#pragma unroll
        for (int m = 0; m < 4; m++) {
            const ulonglong2 p0 = ev[2 * m + 0];
            const ulonglong2 p1 = ev[2 * m + 1];
            ffma2(a0, p0.x, ETp[4 * m + 0]);
            ffma2(a1, p0.y, ETp[4 * m + 1]);
            ffma2(a2, p1.x, ETp[4 * m + 2]);
            ffma2(a3, p1.y, ETp[4 * m + 3]);
        }
        float slo, shi;
        unpack2(fadd2(fadd2(a0, a1), fadd2(a2, a3)), slo, shi);
        float s = slo + shi;
        s += __shfl_xor_sync(0xffffffffu, s, 16);
        if (lane < 16) Esh[1][col] = ms * s;
        __syncthreads();
    }

    // logZ = (R + lg2(sum_j v_last[j])) * ln2. Final vector in Esh[steps & 1].
    float fs = (tid < N_) ? Esh[steps & 1][tid] : 0.0f;
#pragma unroll
    for (int off = 16; off; off >>= 1)
        fs += __shfl_xor_sync(0xffffffffu, fs, off);
    if (lane == 0) red[wid] = fs;
    __syncthreads();
    const float logZ =
        (R + lg2(red[0] + red[1] + red[2] + red[3])) * LN2;

    // Sequence score: unary (t in [0,len)) + binary (t in [1,len)).
    const int* btags = tags + b * T_;
    float sc = 0.0f;
    for (int k = tid; k < len; k += 128)
        sc += emit[k * N_ + btags[k]];
    for (int k = tid + 1; k < len; k += 128)
        sc += trans[btags[k - 1] * N_ + btags[k]];

#pragma unroll
    for (int off = 16; off; off >>= 1)
        sc += __shfl_xor_sync(0xffffffffu, sc, off);
    __syncthreads();               // all logZ reads of red must complete first
    if (lane == 0) red[wid] = sc;
    __syncthreads();
    if (tid == 0)
        out[b] = (red[0] + red[1] + red[2] + red[3]) - logZ;
}

extern "C" void kernel_launch(void* const* d_in, const int* in_sizes, int n_in,
                              void* d_out, int out_size) {
    const float* inputs = (const float*)d_in[0];   // [512, 512, 64] f32
    const float* trans  = (const float*)d_in[1];   // [64, 64] f32
    const int*   tags   = (const int*)d_in[2];     // [512, 512] i32
    const int*   lens   = (const int*)d_in[3];     // [512] i32
    float*       out    = (float*)d_out;           // [512 + 4096] f32

    crf_fwd<<<B_, 128>>>(inputs, trans, tags, lens, out);
}

// round 8
// speedup vs baseline: 1.1345x; 1.0269x over previous
#include <cuda_runtime.h>
#include <cuda_bf16.h>

#define B_ 512
#define T_ 512
#define N_ 64

#define L2E 1.4426950408889634f   // log2(e)
#define LN2 0.6931471805599453f   // ln(2)

// ---- packed f32x2 + MUFU helpers (sm_103a) ----
__device__ __forceinline__ void ffma2(unsigned long long &d,
                                      unsigned long long a,
                                      unsigned long long b) {
    asm("fma.rn.f32x2 %0, %1, %2, %0;" : "+l"(d) : "l"(a), "l"(b));
}
__device__ __forceinline__ unsigned long long fadd2(unsigned long long a,
                                                    unsigned long long b) {
    unsigned long long d;
    asm("add.rn.f32x2 %0, %1, %2;" : "=l"(d) : "l"(a), "l"(b));
    return d;
}
__device__ __forceinline__ unsigned long long pack2(float lo, float hi) {
    unsigned long long d;
    asm("mov.b64 %0, {%1, %2};" : "=l"(d) : "f"(lo), "f"(hi));
    return d;
}
__device__ __forceinline__ void unpack2(unsigned long long v, float &lo, float &hi) {
    asm("mov.b64 {%0, %1}, %2;" : "=f"(lo), "=f"(hi) : "l"(v));
}
__device__ __forceinline__ float ex2(float x) {
    float r; asm("ex2.approx.f32 %0, %1;" : "=f"(r) : "f"(x)); return r;
}
__device__ __forceinline__ float lg2(float x) {
    float r; asm("lg2.approx.f32 %0, %1;" : "=f"(r) : "f"(x)); return r;
}
__device__ __forceinline__ void gbar(int id) {
    asm volatile("bar.sync %0, 128;" :: "r"(id) : "memory");
}

// FORWARD-BACKWARD split: one batch per 256-thread block.
//   warps 0-3 (group 0): v_t = m_t o (A^T v_{t-1}),  t = 1..mid      (fwd)
//   warps 4-7 (group 1): u_t = m_t o (A u_{t+1}),    t = L-1..mid+1,
//                        then beta_mid = A u_{mid+1}  (emission = 0)  (bwd)
//   Z = sum_i v_mid[i] * beta_mid[i]   -- EXACT; serial depth halved 511->256.
// Both groups run the IDENTICAL inner loop (round-7 tuned: unroll-2, exact
// power-of-2 rescale every other step, packed FFMA2 half-GEMV + shfl combine);
// only the register matrix (A^T vs A) and emission index order differ.
// Groups sync with private named barriers; one __syncthreads at the join.
__global__ __launch_bounds__(256) void crf_fb(
    const float* __restrict__ inputs,   // [B, T, N]
    const float* __restrict__ trans,    // [N, N]
    const int*   __restrict__ tags,     // [B, T]
    const int*   __restrict__ lens,     // [B]
    float*       __restrict__ out)      // [B + N*N]
{
    const int b    = blockIdx.x;
    const int tid  = threadIdx.x;
    const int grp  = tid >> 7;                 // 0 = forward, 1 = backward
    const int gt   = tid & 127;                // thread within group
    const int wid  = gt >> 5;
    const int lane = gt & 31;
    const int col  = 16 * wid + (lane & 15);   // owned output index (col / row)
    const int i0   = (lane >> 4) << 5;         // contraction-half base: 0 or 32
    const int barid = grp + 1;

    __shared__ __align__(16) float Esh[2][2][68];   // [group][buf][vec]
    __shared__ float Rsh[2];
    __shared__ float redD[2];
    __shared__ float redS[8];

    // Passthrough copy of transition_params (512 blocks x 8 elems = 4096).
    if (tid < 8) {
        const int idx = b * 8 + tid;
        out[B_ + idx] = trans[idx];
    }

    // Register matrix: group 0 -> A^T columns (exp2(trans[i][col])),
    //                  group 1 -> A rows      (exp2(trans[col][j])).
    unsigned long long ETp[16];
#pragma unroll
    for (int m = 0; m < 16; m++) {
        const int ia = grp ? (col * N_ + i0 + 2 * m) : ((i0 + 2 * m) * N_ + col);
        const int ib = grp ? (col * N_ + i0 + 2 * m + 1) : ((i0 + 2 * m + 1) * N_ + col);
        ETp[m] = pack2(ex2(trans[ia] * L2E), ex2(trans[ib] * L2E));
    }

    const float* emit = inputs + (size_t)b * T_ * N_;
    const int len = lens[b];
    const int L = (len > 1) ? (len - 1) : 0;   // last alpha index
    const int fsteps = L >> 1;                 // forward GEMV count (mid = fsteps)
    const int ns = grp ? (L - fsteps) : fsteps;        // my GEMV count
    const int ne = grp ? (ns - 1) : ns;        // last k with a real emission
    const int st = grp ? L : 0;                // emission row at k=0
    const int dr = grp ? -1 : 1;               // row direction

    float (*V)[68] = Esh[grp];                 // my double buffer

    // Init vector into V[0] (+ my accumulated log2 shift R).
    float R;
    if (grp == 0) {
        const float r0 = __ldg(&emit[0]) * L2E;
        R = r0;
        if (gt < 64) V[0][gt] = ex2(fmaf(emit[gt], L2E, -r0));
    } else if (ns > 0) {
        const float r0 = __ldg(&emit[(size_t)L * N_]) * L2E;
        R = r0;
        if (gt < 64) V[0][gt] = ex2(fmaf(emit[(size_t)L * N_ + gt], L2E, -r0));
    } else {
        R = 0.0f;
        if (gt < 64) V[0][gt] = 1.0f;          // beta = ones when no bwd steps
    }

    // Emission prefetch for my column, one unrolled pair ahead.
    float ecA = (1 <= ne) ? emit[(st + dr) * N_ + col] : 0.0f;
    float ecB = (2 <= ne) ? emit[(st + 2 * dr) * N_ + col] : 0.0f;

    gbar(barid);

    int k = 1;
    for (; k + 1 <= ns; k += 2) {
        const float eA = (k + 2 <= ne) ? emit[(st + dr * (k + 2)) * N_ + col] : 0.0f;
        const float eB = (k + 3 <= ne) ? emit[(st + dr * (k + 3)) * N_ + col] : 0.0f;

        // ---- step A (rescaled, exact power-of-2 shift): V[0] -> V[1] ----
        {
            const float E0 = V[0][0];
            const float q = (float)((int)((__float_as_uint(E0) >> 23) & 0xFF) - 121);
            const float ms = ex2(fmaf(ecA, L2E, -q));
            R += q;

            const ulonglong2* ev = reinterpret_cast<const ulonglong2*>(&V[0][i0]);
            unsigned long long a0 = 0ull, a1 = 0ull, a2 = 0ull, a3 = 0ull;
#pragma unroll
            for (int m = 0; m < 4; m++) {
                const ulonglong2 p0 = ev[2 * m + 0];
                const ulonglong2 p1 = ev[2 * m + 1];
                ffma2(a0, p0.x, ETp[4 * m + 0]);
                ffma2(a1, p0.y, ETp[4 * m + 1]);
                ffma2(a2, p1.x, ETp[4 * m + 2]);
                ffma2(a3, p1.y, ETp[4 * m + 3]);
            }
            float slo, shi;
            unpack2(fadd2(fadd2(a0, a1), fadd2(a2, a3)), slo, shi);
            float s = slo + shi;
            s += __shfl_xor_sync(0xffffffffu, s, 16);
            if (lane < 16) V[1][col] = ms * s;
            gbar(barid);
        }

        // ---- step B (no rescale): V[1] -> V[0] ----
        {
            const float ms = ex2(ecB * L2E);

            const ulonglong2* ev = reinterpret_cast<const ulonglong2*>(&V[1][i0]);
            unsigned long long a0 = 0ull, a1 = 0ull, a2 = 0ull, a3 = 0ull;
#pragma unroll
            for (int m = 0; m < 4; m++) {
                const ulonglong2 p0 = ev[2 * m + 0];
                const ulonglong2 p1 = ev[2 * m + 1];
                ffma2(a0, p0.x, ETp[4 * m + 0]);
                ffma2(a1, p0.y, ETp[4 * m + 1]);
                ffma2(a2, p1.x, ETp[4 * m + 2]);
                ffma2(a3, p1.y, ETp[4 * m + 3]);
            }
            float slo, shi;
            unpack2(fadd2(fadd2(a0, a1), fadd2(a2, a3)), slo, shi);
            float s = slo + shi;
            s += __shfl_xor_sync(0xffffffffu, s, 16);
            if (lane < 16) V[0][col] = ms * s;
            gbar(barid);
        }

        ecA = eA;
        ecB = eB;
    }

    // Odd leftover step (k == ns): rescaled, V[0] -> V[1].
    if (k <= ns) {
        const float E0 = V[0][0];
        const float q = (float)((int)((__float_as_uint(E0) >> 23) & 0xFF) - 121);
        const float ms = ex2(fmaf(ecA, L2E, -q));
        R += q;

        const ulonglong2* ev = reinterpret_cast<const ulonglong2*>(&V[0][i0]);
        unsigned long long a0 = 0ull, a1 = 0ull, a2 = 0ull, a3 = 0ull;
#pragma unroll
        for (int m = 0; m < 4; m++) {
            const ulonglong2 p0 = ev[2 * m + 0];
            const ulonglong2 p1 = ev[2 * m + 1];
            ffma2(a0, p0.x, ETp[4 * m + 0]);
            ffma2(a1, p0.y, ETp[4 * m + 1]);
            ffma2(a2, p1.x, ETp[4 * m + 2]);
            ffma2(a3, p1.y, ETp[4 * m + 3]);
        }
        float slo, shi;
        unpack2(fadd2(fadd2(a0, a1), fadd2(a2, a3)), slo, shi);
        float s = slo + shi;
        s += __shfl_xor_sync(0xffffffffu, s, 16);
        if (lane < 16) V[1][col] = ms * s;
        gbar(barid);
    }

    // ---- join: Z = sum_i v_mid[i] * beta_mid[i] ----
    if (gt == 0) Rsh[grp] = R;
    __syncthreads();

    const int fpar = fsteps & 1;
    const int bpar = (L - fsteps) & 1;
    float dv = (tid < 64) ? Esh[0][fpar][tid] * Esh[1][bpar][tid] : 0.0f;
#pragma unroll
    for (int off = 16; off; off >>= 1)
        dv += __shfl_xor_sync(0xffffffffu, dv, off);
    if (tid < 64 && (tid & 31) == 0) redD[tid >> 5] = dv;

    // Sequence score over all 256 threads: unary [0,len), binary [1,len).
    const int* btags = tags + b * T_;
    float sc = 0.0f;
    for (int q = tid; q < len; q += 256)
        sc += emit[q * N_ + btags[q]];
    for (int q = tid + 1; q < len; q += 256)
        sc += trans[btags[q - 1] * N_ + btags[q]];
#pragma unroll
    for (int off = 16; off; off >>= 1)
        sc += __shfl_xor_sync(0xffffffffu, sc, off);
    if ((tid & 31) == 0) redS[tid >> 5] = sc;
    __syncthreads();

    if (tid == 0) {
        const float logZ = (Rsh[0] + Rsh[1] + lg2(redD[0] + redD[1])) * LN2;
        const float sTot = ((redS[0] + redS[1]) + (redS[2] + redS[3]))
                         + ((redS[4] + redS[5]) + (redS[6] + redS[7]));
        out[b] = sTot - logZ;
    }
}

extern "C" void kernel_launch(void* const* d_in, const int* in_sizes, int n_in,
                              void* d_out, int out_size) {
    const float* inputs = (const float*)d_in[0];   // [512, 512, 64] f32
    const float* trans  = (const float*)d_in[1];   // [64, 64] f32
    const int*   tags   = (const int*)d_in[2];     // [512, 512] i32
    const int*   lens   = (const int*)d_in[3];     // [512] i32
    float*       out    = (float*)d_out;           // [512 + 4096] f32

    crf_fb<<<B_, 256>>>(inputs, trans, tags, lens, out);
}

// round 9
// speedup vs baseline: 1.1990x; 1.0568x over previous
#include <cuda_runtime.h>
#include <cuda_bf16.h>

#define B_ 512
#define T_ 512
#define N_ 64

#define L2E 1.4426950408889634f   // log2(e)
#define LN2 0.6931471805599453f   // ln(2)

// ---- packed f32x2 + MUFU helpers (sm_103a) ----
__device__ __forceinline__ void ffma2(unsigned long long &d,
                                      unsigned long long a,
                                      unsigned long long b) {
    asm("fma.rn.f32x2 %0, %1, %2, %0;" : "+l"(d) : "l"(a), "l"(b));
}
__device__ __forceinline__ unsigned long long fadd2(unsigned long long a,
                                                    unsigned long long b) {
    unsigned long long d;
    asm("add.rn.f32x2 %0, %1, %2;" : "=l"(d) : "l"(a), "l"(b));
    return d;
}
__device__ __forceinline__ unsigned long long pack2(float lo, float hi) {
    unsigned long long d;
    asm("mov.b64 %0, {%1, %2};" : "=l"(d) : "f"(lo), "f"(hi));
    return d;
}
__device__ __forceinline__ void unpack2(unsigned long long v, float &lo, float &hi) {
    asm("mov.b64 {%0, %1}, %2;" : "=f"(lo), "=f"(hi) : "l"(v));
}
__device__ __forceinline__ float ex2(float x) {
    float r; asm("ex2.approx.f32 %0, %1;" : "=f"(r) : "f"(x)); return r;
}
__device__ __forceinline__ float lg2(float x) {
    float r; asm("lg2.approx.f32 %0, %1;" : "=f"(r) : "f"(x)); return r;
}
__device__ __forceinline__ void gbar(int id) {
    asm volatile("bar.sync %0, 64;" :: "r"(id) : "memory");
}

// Full 64-MAC column GEMV: s = sum_i v[i] * ET[i], packed f32x2,
// 16 broadcast LDS.128 + 32 FFMA2, 8 accumulators (depth 4).
__device__ __forceinline__ float gemv64(const float* __restrict__ vsrc,
                                        const unsigned long long* __restrict__ ETp) {
    const ulonglong2* ev = reinterpret_cast<const ulonglong2*>(vsrc);
    unsigned long long a0 = 0ull, a1 = 0ull, a2 = 0ull, a3 = 0ull;
    unsigned long long a4 = 0ull, a5 = 0ull, a6 = 0ull, a7 = 0ull;
#pragma unroll
    for (int m = 0; m < 4; m++) {
        const ulonglong2 p0 = ev[4 * m + 0];
        const ulonglong2 p1 = ev[4 * m + 1];
        const ulonglong2 p2 = ev[4 * m + 2];
        const ulonglong2 p3 = ev[4 * m + 3];
        ffma2(a0, p0.x, ETp[8 * m + 0]);
        ffma2(a1, p0.y, ETp[8 * m + 1]);
        ffma2(a2, p1.x, ETp[8 * m + 2]);
        ffma2(a3, p1.y, ETp[8 * m + 3]);
        ffma2(a4, p2.x, ETp[8 * m + 4]);
        ffma2(a5, p2.y, ETp[8 * m + 5]);
        ffma2(a6, p3.x, ETp[8 * m + 6]);
        ffma2(a7, p3.y, ETp[8 * m + 7]);
    }
    const unsigned long long sA =
        fadd2(fadd2(fadd2(a0, a1), fadd2(a2, a3)),
              fadd2(fadd2(a4, a5), fadd2(a6, a7)));
    float slo, shi;
    unpack2(sA, slo, shi);
    return slo + shi;
}

// FORWARD-BACKWARD split with 2-WARP GANGS: one batch per 128-thread block.
//   warps 0-1 (gang 0): v_t = m_t o (A^T v_{t-1}),  t = 1..mid        (fwd)
//   warps 2-3 (gang 1): u_t = m_t o (A u_{t+1}),    t = L-1..mid+1,
//                       then beta_mid = A u_{mid+1}  (no emission)     (bwd)
//   Z = sum_i v_mid[i] * beta_mid[i]  -- EXACT; serial depth 511 -> 256.
// Thread gt owns FULL column gt (32 packed f32x2 matrix regs): no shfl
// combine, no write predicate; 2-warp barrier minimizes straggler delay and
// resident-warp contention (3.46 warps/SMSP). Unroll-2 with exact power-of-2
// rescale every other step (validated rounds 7-8).
__global__ __launch_bounds__(128) void crf_fb(
    const float* __restrict__ inputs,   // [B, T, N]
    const float* __restrict__ trans,    // [N, N]
    const int*   __restrict__ tags,     // [B, T]
    const int*   __restrict__ lens,     // [B]
    float*       __restrict__ out)      // [B + N*N]
{
    const int b    = blockIdx.x;
    const int tid  = threadIdx.x;
    const int grp  = tid >> 6;                 // 0 = forward, 1 = backward
    const int gt   = tid & 63;                 // owned column / row index
    const int barid = grp + 1;

    __shared__ __align__(16) float Esh[2][2][68];   // [group][buf][vec]
    __shared__ float Rsh[2];
    __shared__ float redD[2];
    __shared__ float redS[4];

    // Passthrough copy of transition_params (512 blocks x 8 elems = 4096).
    if (tid < 8) {
        const int idx = b * 8 + tid;
        out[B_ + idx] = trans[idx];
    }

    // Register matrix, packed over the contraction index i:
    //   gang 0 (fwd): ET[i] = exp2(trans[i][gt] * L2E)   (A^T column gt)
    //   gang 1 (bwd): ET[i] = exp2(trans[gt][i] * L2E)   (A row gt)
    unsigned long long ETp[32];
#pragma unroll
    for (int m = 0; m < 32; m++) {
        const int ia = grp ? (gt * N_ + 2 * m)     : ((2 * m) * N_ + gt);
        const int ib = grp ? (gt * N_ + 2 * m + 1) : ((2 * m + 1) * N_ + gt);
        ETp[m] = pack2(ex2(trans[ia] * L2E), ex2(trans[ib] * L2E));
    }

    const float* emit = inputs + (size_t)b * T_ * N_;
    const int len = lens[b];
    const int L = (len > 1) ? (len - 1) : 0;   // last alpha index
    const int fsteps = L >> 1;                 // forward GEMV count (mid = fsteps)
    const int ns = grp ? (L - fsteps) : fsteps;   // my GEMV count
    const int ne = grp ? (ns - 1) : ns;        // last k with a real emission
    const int st = grp ? L : 0;                // emission row at k=0
    const int dr = grp ? -1 : 1;               // row direction

    float (*V)[68] = Esh[grp];                 // my double buffer

    // Init vector into V[0] (+ my accumulated log2 shift R).
    float R;
    if (grp == 0) {
        const float r0 = __ldg(&emit[0]) * L2E;
        R = r0;
        V[0][gt] = ex2(fmaf(emit[gt], L2E, -r0));
    } else if (ns > 0) {
        const float r0 = __ldg(&emit[(size_t)L * N_]) * L2E;
        R = r0;
        V[0][gt] = ex2(fmaf(emit[(size_t)L * N_ + gt], L2E, -r0));
    } else {
        R = 0.0f;
        V[0][gt] = 1.0f;                       // beta = ones when no bwd steps
    }

    // Emission prefetch for my column, one unrolled pair ahead.
    float ecA = (1 <= ne) ? emit[(st + dr) * N_ + gt] : 0.0f;
    float ecB = (2 <= ne) ? emit[(st + 2 * dr) * N_ + gt] : 0.0f;

    gbar(barid);

    int k = 1;
    for (; k + 1 <= ns; k += 2) {
        const float eA = (k + 2 <= ne) ? emit[(st + dr * (k + 2)) * N_ + gt] : 0.0f;
        const float eB = (k + 3 <= ne) ? emit[(st + dr * (k + 3)) * N_ + gt] : 0.0f;

        // ---- step A (rescaled, exact power-of-2 shift): V[0] -> V[1] ----
        {
            const float E0 = V[0][0];
            const float q = (float)((int)((__float_as_uint(E0) >> 23) & 0xFF) - 121);
            const float ms = ex2(fmaf(ecA, L2E, -q));
            R += q;
            const float s = gemv64(&V[0][0], ETp);
            V[1][gt] = ms * s;
            gbar(barid);
        }

        // ---- step B (no rescale): V[1] -> V[0] ----
        {
            const float ms = ex2(ecB * L2E);
            const float s = gemv64(&V[1][0], ETp);
            V[0][gt] = ms * s;
            gbar(barid);
        }

        ecA = eA;
        ecB = eB;
    }

    // Odd leftover step (k == ns): rescaled, V[0] -> V[1].
    if (k <= ns) {
        const float E0 = V[0][0];
        const float q = (float)((int)((__float_as_uint(E0) >> 23) & 0xFF) - 121);
        const float ms = ex2(fmaf(ecA, L2E, -q));
        R += q;
        const float s = gemv64(&V[0][0], ETp);
        V[1][gt] = ms * s;
        gbar(barid);
    }

    // ---- join: Z = sum_i v_mid[i] * beta_mid[i] ----
    if (gt == 0) Rsh[grp] = R;
    __syncthreads();

    const int fpar = fsteps & 1;
    const int bpar = (L - fsteps) & 1;
    float dv = (tid < 64) ? Esh[0][fpar][tid] * Esh[1][bpar][tid] : 0.0f;
#pragma unroll
    for (int off = 16; off; off >>= 1)
        dv += __shfl_xor_sync(0xffffffffu, dv, off);
    if (tid < 64 && (tid & 31) == 0) redD[tid >> 5] = dv;

    // Sequence score over all 128 threads: unary [0,len), binary [1,len).
    const int* btags = tags + b * T_;
    float sc = 0.0f;
    for (int q = tid; q < len; q += 128)
        sc += emit[q * N_ + btags[q]];
    for (int q = tid + 1; q < len; q += 128)
        sc += trans[btags[q - 1] * N_ + btags[q]];
#pragma unroll
    for (int off = 16; off; off >>= 1)
        sc += __shfl_xor_sync(0xffffffffu, sc, off);
    if ((tid & 31) == 0) redS[tid >> 5] = sc;
    __syncthreads();

    if (tid == 0) {
        const float logZ = (Rsh[0] + Rsh[1] + lg2(redD[0] + redD[1])) * LN2;
        out[b] = ((redS[0] + redS[1]) + (redS[2] + redS[3])) - logZ;
    }
}

extern "C" void kernel_launch(void* const* d_in, const int* in_sizes, int n_in,
                              void* d_out, int out_size) {
    const float* inputs = (const float*)d_in[0];   // [512, 512, 64] f32
    const float* trans  = (const float*)d_in[1];   // [64, 64] f32
    const int*   tags   = (const int*)d_in[2];     // [512, 512] i32
    const int*   lens   = (const int*)d_in[3];     // [512] i32
    float*       out    = (float*)d_out;           // [512 + 4096] f32

    crf_fb<<<B_, 128>>>(inputs, trans, tags, lens, out);
}